// round 3
// baseline (speedup 1.0000x reference)
#include <cuda_runtime.h>
#include <cstdint>

// Problem constants (fixed shapes for this problem instance)
#define N_MASKS 128
#define HM 28
#define WM 28
#define IMG_H 800
#define IMG_W 1280
#define IN_W 1184.0f
#define IN_H 736.0f

// Per-mask affine params: px = ax*(x+0.5) + bx ; py = ay*(y+0.5) + by
__device__ float4 g_params[N_MASKS];

__global__ void compute_params_kernel(const float* __restrict__ boxes) {
    int n = threadIdx.x;
    if (n >= N_MASKS) return;
    const float sx = (float)IMG_W / IN_W;
    const float sy = (float)IMG_H / IN_H;
    float x0 = fminf(fmaxf(boxes[4 * n + 0] * sx, 0.0f), (float)IMG_W);
    float y0 = fminf(fmaxf(boxes[4 * n + 1] * sy, 0.0f), (float)IMG_H);
    float x1 = fminf(fmaxf(boxes[4 * n + 2] * sx, 0.0f), (float)IMG_W);
    float y1 = fminf(fmaxf(boxes[4 * n + 3] * sy, 0.0f), (float)IMG_H);
    // px = (x+0.5 - x0) * WM/(x1-x0) - 0.5  ==  ax*(x+0.5) + bx
    float ax = (float)WM / (x1 - x0);
    float ay = (float)HM / (y1 - y0);
    float bx = -x0 * ax - 0.5f;
    float by = -y0 * ay - 0.5f;
    g_params[n] = make_float4(ax, bx, ay, by);
}

// One thread -> 4 consecutive output pixels (float4 store).
// blockIdx.y = mask index n. blockIdx.x*blockDim.x+tid = pixel4 index in image.
__global__ void __launch_bounds__(256) paste_kernel(const float* __restrict__ masks,
                                                    float* __restrict__ out) {
    const int W4 = IMG_W / 4;                       // 320
    int p = blockIdx.x * blockDim.x + threadIdx.x;  // [0, IMG_H*W4)
    if (p >= IMG_H * W4) return;
    int n = blockIdx.y;

    int y  = p / W4;
    int x4 = (p - y * W4) * 4;

    float4 prm = g_params[n];
    float py = prm.z * ((float)y + 0.5f) + prm.w;

    float* dst = out + ((size_t)n * IMG_H + y) * IMG_W + x4;

    float4 outv = make_float4(0.f, 0.f, 0.f, 0.f);

    // Fast path: entire row of this mask is outside vertical support -> zeros.
    if (py > -1.0f && py < (float)HM) {
        float fy  = floorf(py);
        int   iy  = (int)fy;
        float wy1 = py - fy;
        float wy0 = 1.0f - wy1;
        // py in (-1, 28) => iy in [-1, 27]
        bool vy0 = (iy >= 0);
        bool vy1 = (iy + 1 < HM);
        float wr0 = vy0 ? wy0 : 0.0f;
        float wr1 = vy1 ? wy1 : 0.0f;

        const float* mbase = masks + (size_t)n * HM * WM;
        const float* r0 = mbase + max(iy, 0) * WM;
        const float* r1 = mbase + min(iy + 1, HM - 1) * WM;

        float res[4];
#pragma unroll
        for (int k = 0; k < 4; k++) {
            float px = prm.x * ((float)(x4 + k) + 0.5f) + prm.y;
            float v = 0.0f;
            if (px > -1.0f && px < (float)WM) {
                float fx  = floorf(px);
                int   ix  = (int)fx;
                float wx1 = px - fx;
                float wx0 = 1.0f - wx1;
                bool vx0 = (ix >= 0);
                bool vx1 = (ix + 1 < WM);
                float w0 = vx0 ? wx0 : 0.0f;
                float w1 = vx1 ? wx1 : 0.0f;
                int ix0 = max(ix, 0);
                int ix1 = min(ix + 1, WM - 1);
                float top = w0 * __ldg(r0 + ix0) + w1 * __ldg(r0 + ix1);
                float bot = w0 * __ldg(r1 + ix0) + w1 * __ldg(r1 + ix1);
                v = wr0 * top + wr1 * bot;
            }
            res[k] = v;
        }
        outv = make_float4(res[0], res[1], res[2], res[3]);
    }

    *reinterpret_cast<float4*>(dst) = outv;
}

extern "C" void kernel_launch(void* const* d_in, const int* in_sizes, int n_in,
                              void* d_out, int out_size) {
    const float* masks = (const float*)d_in[0];
    const float* boxes = (const float*)d_in[1];
    float* out = (float*)d_out;

    compute_params_kernel<<<1, N_MASKS>>>(boxes);

    const int pixels4 = IMG_H * (IMG_W / 4);        // 256000
    dim3 grid((pixels4 + 255) / 256, N_MASKS);      // (1000, 128)
    paste_kernel<<<grid, 256>>>(masks, out);
}

// round 5
// speedup vs baseline: 1.1336x; 1.1336x over previous
#include <cuda_runtime.h>
#include <cstdint>

// Problem constants (fixed shapes for this problem instance)
#define N_MASKS 128
#define HM 28
#define WM 28
#define IMG_H 800
#define IMG_W 1280
#define IN_W 1184.0f
#define IN_H 736.0f
#define ROWS_PER_BLOCK 4

// Per-mask affine params: px = ax*(x+0.5) + bx ; py = ay*(y+0.5) + by
__device__ float4 g_params[N_MASKS];

__global__ void compute_params_kernel(const float* __restrict__ boxes) {
    int n = threadIdx.x;
    if (n >= N_MASKS) return;
    const float sx = (float)IMG_W / IN_W;
    const float sy = (float)IMG_H / IN_H;
    float x0 = fminf(fmaxf(boxes[4 * n + 0] * sx, 0.0f), (float)IMG_W);
    float y0 = fminf(fmaxf(boxes[4 * n + 1] * sy, 0.0f), (float)IMG_H);
    float x1 = fminf(fmaxf(boxes[4 * n + 2] * sx, 0.0f), (float)IMG_W);
    float y1 = fminf(fmaxf(boxes[4 * n + 3] * sy, 0.0f), (float)IMG_H);
    float ax = (float)WM / (x1 - x0);
    float ay = (float)HM / (y1 - y0);
    float bx = -x0 * ax - 0.5f;
    float by = -y0 * ay - 0.5f;
    g_params[n] = make_float4(ax, bx, ay, by);
}

// Block = 4 consecutive rows of one mask. 320 threads, thread t owns pixels
// [4t, 4t+3] in each of the 4 rows -> 4x STG.128 per thread, horizontal
// interp weights computed once and reused across rows.
__global__ void __launch_bounds__(320) paste_kernel(const float* __restrict__ masks,
                                                    float* __restrict__ out) {
    const int n  = blockIdx.y;
    const int y0 = blockIdx.x * ROWS_PER_BLOCK;
    const int x4 = threadIdx.x * 4;

    float4 prm = g_params[n];   // ax, bx, ay, by

    float* dst = out + ((size_t)n * IMG_H + y0) * IMG_W + x4;
    const float4 zero = make_float4(0.f, 0.f, 0.f, 0.f);

    // Vertical support for this block's 4 rows (py monotonically increasing: ay > 0)
    float py0 = prm.z * ((float)y0 + 0.5f) + prm.w;
    float py3 = py0 + 3.0f * prm.z;
    bool rows_active = (py3 > -1.0f) & (py0 < (float)HM);

    // Horizontal support for this thread's 4 pixels (ax > 0)
    float px0 = prm.x * ((float)x4 + 0.5f) + prm.y;
    float px3 = px0 + 3.0f * prm.x;
    bool cols_active = (px3 > -1.0f) & (px0 < (float)WM);

    if (!(rows_active & cols_active)) {
        // Fast path: 4 independent streaming zero stores (MLP=4).
#pragma unroll
        for (int r = 0; r < ROWS_PER_BLOCK; r++)
            __stcs(reinterpret_cast<float4*>(dst + (size_t)r * IMG_W), zero);
        return;
    }

    // ---- horizontal precompute (shared by all 4 rows) ----
    int   ix0[4], ix1[4];
    float w0[4], w1[4];
#pragma unroll
    for (int k = 0; k < 4; k++) {
        float px  = px0 + (float)k * prm.x;
        float fx  = floorf(px);
        int   ix  = (int)fx;             // saturating cvt on CUDA; clamped below
        float wx1 = px - fx;
        float wx0 = 1.0f - wx1;
        bool inr = (px > -1.0f) & (px < (float)WM);
        bool vx0 = inr & (ix >= 0);
        bool vx1 = inr & (ix + 1 < WM);
        w0[k]  = vx0 ? wx0 : 0.0f;
        w1[k]  = vx1 ? wx1 : 0.0f;
        ix0[k] = min(max(ix, 0), WM - 1);
        ix1[k] = min(max(ix + 1, 0), WM - 1);
    }

    const float* mbase = masks + (size_t)n * (HM * WM);

#pragma unroll
    for (int r = 0; r < ROWS_PER_BLOCK; r++) {
        float py  = py0 + (float)r * prm.z;
        float fy  = floorf(py);
        int   iy  = (int)fy;
        float wy1 = py - fy;
        float wy0 = 1.0f - wy1;
        bool inr = (py > -1.0f) & (py < (float)HM);
        float wr0 = (inr & (iy >= 0))      ? wy0 : 0.0f;
        float wr1 = (inr & (iy + 1 < HM)) ? wy1 : 0.0f;
        const float* r0 = mbase + min(max(iy, 0), HM - 1) * WM;
        const float* r1 = mbase + min(max(iy + 1, 0), HM - 1) * WM;

        float res[4];
#pragma unroll
        for (int k = 0; k < 4; k++) {
            float top = w0[k] * __ldg(r0 + ix0[k]) + w1[k] * __ldg(r0 + ix1[k]);
            float bot = w0[k] * __ldg(r1 + ix0[k]) + w1[k] * __ldg(r1 + ix1[k]);
            res[k] = wr0 * top + wr1 * bot;
        }
        __stcs(reinterpret_cast<float4*>(dst + (size_t)r * IMG_W),
               make_float4(res[0], res[1], res[2], res[3]));
    }
}

extern "C" void kernel_launch(void* const* d_in, const int* in_sizes, int n_in,
                              void* d_out, int out_size) {
    const float* masks = (const float*)d_in[0];
    const float* boxes = (const float*)d_in[1];
    float* out = (float*)d_out;

    compute_params_kernel<<<1, N_MASKS>>>(boxes);

    dim3 grid(IMG_H / ROWS_PER_BLOCK, N_MASKS);   // (200, 128)
    paste_kernel<<<grid, 320>>>(masks, out);
}